// round 2
// baseline (speedup 1.0000x reference)
#include <cuda_runtime.h>
#include <math.h>

// ---------------- problem constants ----------------
#define NMAX 100000
#define EMAX 3200000
#define DHID 128
#define DOUT 64

// ---------------- static scratch (allocation-free) ----------------
__device__ float g_h1  [NMAX * DHID];   // layer1 GEMM out
__device__ float g_agg1[NMAX * DHID];   // layer1 aggregation -> relu+bias in place
__device__ float g_h2  [NMAX * DOUT];   // layer2 GEMM out
__device__ float g_agg2[NMAX * DOUT];   // layer2 aggregation
__device__ float g_as  [NMAX];
__device__ float g_ad  [NMAX];
__device__ float g_m   [NMAX];
__device__ float g_s   [NMAX];
__device__ float g_p   [EMAX + NMAX];   // per-edge exp(e - m[dst])

// ---------------- fp32 GEMM: H[N,FOUT] = X[N,128] @ W[128,FOUT] ----------------
// Block = 32 rows x FOUT cols, FOUT*2 threads, each thread a 4x4 register tile.
template<int FOUT>
__global__ void k_gemm(const float* __restrict__ X, const float* __restrict__ W,
                       float* __restrict__ H, int N) {
    constexpr int K  = 128;
    constexpr int NT = FOUT * 2;
    constexpr int CT = FOUT / 4;
    extern __shared__ float smem[];
    float*  sW  = smem;              // K * FOUT
    float*  sX  = smem + K * FOUT;   // 32 * K
    float4* sW4 = (float4*)sW;
    float4* sX4 = (float4*)sX;

    int tid  = threadIdx.x;
    int row0 = blockIdx.x * 32;

    for (int i = tid; i < K * FOUT / 4; i += NT) sW4[i] = ((const float4*)W)[i];
    {
        const float4* X4 = (const float4*)(X + (size_t)row0 * K);
        int lim = (N - row0) >= 32 ? 32 * K / 4 : (N - row0) * K / 4;
        for (int i = tid; i < lim; i += NT) sX4[i] = X4[i];
    }
    __syncthreads();

    int tx = tid % CT;
    int ty = tid / CT;          // 0..7 -> rows ty*4 .. ty*4+3
    float acc[4][4];
#pragma unroll
    for (int i = 0; i < 4; i++)
#pragma unroll
        for (int j = 0; j < 4; j++) acc[i][j] = 0.f;

    for (int k = 0; k < K; k += 4) {
#pragma unroll
        for (int kk = 0; kk < 4; kk++) {
            float4 wv = sW4[(k + kk) * CT + tx];
#pragma unroll
            for (int i = 0; i < 4; i++) {
                float xv = sX[(ty * 4 + i) * K + k + kk];
                acc[i][0] += xv * wv.x;
                acc[i][1] += xv * wv.y;
                acc[i][2] += xv * wv.z;
                acc[i][3] += xv * wv.w;
            }
        }
    }

    float4* H4 = (float4*)(H + (size_t)row0 * FOUT);
#pragma unroll
    for (int i = 0; i < 4; i++) {
        int r = ty * 4 + i;
        if (row0 + r < N)
            H4[r * CT + tx] = make_float4(acc[i][0], acc[i][1], acc[i][2], acc[i][3]);
    }
}

// ---------------- per-node attention halves: as = h.a_src, ad = h.a_dst ----------------
template<int F>
__global__ void k_dots(const float* __restrict__ H, const float* __restrict__ avs,
                       const float* __restrict__ avd, int N) {
    int w    = (blockIdx.x * blockDim.x + threadIdx.x) >> 5;
    int lane = threadIdx.x & 31;
    if (w >= N) return;
    const float* h = H + (size_t)w * F;
    float s1 = 0.f, s2 = 0.f;
#pragma unroll
    for (int j = 0; j < F / 32; j++) {
        float hv = h[lane + 32 * j];
        s1 += hv * __ldg(&avs[lane + 32 * j]);
        s2 += hv * __ldg(&avd[lane + 32 * j]);
    }
#pragma unroll
    for (int off = 16; off > 0; off >>= 1) {
        s1 += __shfl_down_sync(0xffffffffu, s1, off);
        s2 += __shfl_down_sync(0xffffffffu, s2, off);
    }
    if (lane == 0) { g_as[w] = s1; g_ad[w] = s2; }
}

// ---------------- fill ----------------
__global__ void k_fill(float* p, float v, int n) {
    int i = blockIdx.x * blockDim.x + threadIdx.x;
    if (i < n) p[i] = v;
}

__device__ __forceinline__ float leaky(float e) {
    return e > 0.f ? e : 0.2f * e;
}

// ---------------- pass A: segment max of edge logits ----------------
__global__ void k_passA(const int* __restrict__ srcp, const int* __restrict__ dstp,
                        int E, int N) {
    int i = blockIdx.x * blockDim.x + threadIdx.x;
    if (i >= E + N) return;
    int s, d;
    if (i < E) { s = srcp[i]; d = dstp[i]; } else { s = d = i - E; }
    float e = leaky(g_as[s] + g_ad[d]);
    if (e >= 0.f) atomicMax((int*)&g_m[d], __float_as_int(e));
    else          atomicMin((unsigned int*)&g_m[d], __float_as_uint(e));
}

// ---------------- pass B: p = exp(e - m[dst]); s[dst] += p ----------------
__global__ void k_passB(const int* __restrict__ srcp, const int* __restrict__ dstp,
                        int E, int N) {
    int i = blockIdx.x * blockDim.x + threadIdx.x;
    if (i >= E + N) return;
    int s, d;
    if (i < E) { s = srcp[i]; d = dstp[i]; } else { s = d = i - E; }
    float e  = leaky(g_as[s] + g_ad[d]);
    float ex = __expf(e - g_m[d]);
    g_p[i] = ex;
    atomicAdd(&g_s[d], ex);
}

// ---------------- pass C: agg[dst] += h[src] * alpha  (one warp per edge) ----------------
template<int F>
__global__ void k_passC(const int* __restrict__ srcp, const int* __restrict__ dstp,
                        const float* __restrict__ H, float* __restrict__ AGG,
                        int E, int N) {
    int w    = (blockIdx.x * blockDim.x + threadIdx.x) >> 5;
    int lane = threadIdx.x & 31;
    if (w >= E + N) return;
    int s, d;
    if (w < E) { s = srcp[w]; d = dstp[w]; } else { s = d = w - E; }
    float alpha = g_p[w] / (g_s[d] + 1e-16f);
    if (F == 128) {
        float4 hv = ((const float4*)(H + (size_t)s * F))[lane];
        float4* dp = ((float4*)(AGG + (size_t)d * F)) + lane;
        asm volatile("red.global.add.v4.f32 [%0], {%1,%2,%3,%4};" ::
                     "l"(dp), "f"(hv.x * alpha), "f"(hv.y * alpha),
                     "f"(hv.z * alpha), "f"(hv.w * alpha) : "memory");
    } else {
        float2 hv = ((const float2*)(H + (size_t)s * F))[lane];
        float2* dp = ((float2*)(AGG + (size_t)d * F)) + lane;
        asm volatile("red.global.add.v2.f32 [%0], {%1,%2};" ::
                     "l"(dp), "f"(hv.x * alpha), "f"(hv.y * alpha) : "memory");
    }
}

// ---------------- relu(agg + b) in place (float4) ----------------
__global__ void k_relu_bias(float* A, const float* __restrict__ b, int n4, int F4) {
    int i = blockIdx.x * blockDim.x + threadIdx.x;
    if (i >= n4) return;
    float4 v  = ((float4*)A)[i];
    const float4 bv = ((const float4*)b)[i % F4];
    v.x = fmaxf(v.x + bv.x, 0.f);
    v.y = fmaxf(v.y + bv.y, 0.f);
    v.z = fmaxf(v.z + bv.z, 0.f);
    v.w = fmaxf(v.w + bv.w, 0.f);
    ((float4*)A)[i] = v;
}

// ---------------- output: out[c] = mean_n agg2[n][c] + b2[c] ----------------
__global__ void k_out_init(float* out, const float* __restrict__ b2) {
    if (threadIdx.x < DOUT) out[threadIdx.x] = b2[threadIdx.x];
}

__global__ void k_mean(const float* __restrict__ A, float* out, int N, float invN) {
    int col    = threadIdx.x & 63;
    int rgrp   = blockIdx.x * (blockDim.x >> 6) + (threadIdx.x >> 6);
    int stride = gridDim.x * (blockDim.x >> 6);
    float sum = 0.f;
    for (int n = rgrp; n < N; n += stride) sum += A[(size_t)n * DOUT + col];
    atomicAdd(&out[col], sum * invN);
}

// ---------------- host ----------------
extern "C" void kernel_launch(void* const* d_in, const int* in_sizes, int n_in,
                              void* d_out, int out_size) {
    const float* x   = (const float*)d_in[0];
    const int*   ei  = (const int*)d_in[1];     // int32! (JAX x64 disabled)
    const float* W1  = (const float*)d_in[2];
    const float* a1s = (const float*)d_in[3];
    const float* a1d = (const float*)d_in[4];
    const float* b1  = (const float*)d_in[5];
    const float* W2  = (const float*)d_in[6];
    const float* a2s = (const float*)d_in[7];
    const float* a2d = (const float*)d_in[8];
    const float* b2  = (const float*)d_in[9];
    float* out = (float*)d_out;

    int N = in_sizes[0] / DHID;   // 100000
    int E = in_sizes[1] / 2;      // 3200000
    const int* srcp = ei;
    const int* dstp = ei + E;

    float *h1, *agg1, *h2, *agg2, *mp, *sp;
    cudaGetSymbolAddress((void**)&h1,   g_h1);
    cudaGetSymbolAddress((void**)&agg1, g_agg1);
    cudaGetSymbolAddress((void**)&h2,   g_h2);
    cudaGetSymbolAddress((void**)&agg2, g_agg2);
    cudaGetSymbolAddress((void**)&mp,   g_m);
    cudaGetSymbolAddress((void**)&sp,   g_s);

    const int smem1 = (128 * 128 + 32 * 128) * 4;  // 81920
    const int smem2 = (128 * 64  + 32 * 128) * 4;  // 49152
    cudaFuncSetAttribute(k_gemm<128>, cudaFuncAttributeMaxDynamicSharedMemorySize, smem1);
    cudaFuncSetAttribute(k_gemm<64>,  cudaFuncAttributeMaxDynamicSharedMemorySize, smem2);

    int EN       = E + N;
    int gemmBlks = (N + 31) / 32;
    int edgeBlks = (EN + 255) / 256;
    int warpBlks = (EN + 7) / 8;        // 8 warps/block in passC
    int dotBlks  = (N + 7) / 8;

    // ---------- layer 1 (F = 128) ----------
    k_gemm<128><<<gemmBlks, 256, smem1>>>(x, W1, h1, N);
    k_dots<128><<<dotBlks, 256>>>(h1, a1s, a1d, N);
    k_fill<<<(N + 255) / 256, 256>>>(mp, -INFINITY, N);
    k_fill<<<(N + 255) / 256, 256>>>(sp, 0.f, N);
    k_fill<<<(N * DHID + 255) / 256, 256>>>(agg1, 0.f, N * DHID);
    k_passA<<<edgeBlks, 256>>>(srcp, dstp, E, N);
    k_passB<<<edgeBlks, 256>>>(srcp, dstp, E, N);
    k_passC<128><<<warpBlks, 256>>>(srcp, dstp, h1, agg1, E, N);
    k_relu_bias<<<(N * DHID / 4 + 255) / 256, 256>>>(agg1, b1, N * DHID / 4, DHID / 4);

    // ---------- layer 2 (F = 64) ----------
    k_gemm<64><<<gemmBlks, 128, smem2>>>(agg1, W2, h2, N);
    k_dots<64><<<dotBlks, 256>>>(h2, a2s, a2d, N);
    k_fill<<<(N + 255) / 256, 256>>>(mp, -INFINITY, N);
    k_fill<<<(N + 255) / 256, 256>>>(sp, 0.f, N);
    k_fill<<<(N * DOUT + 255) / 256, 256>>>(agg2, 0.f, N * DOUT);
    k_passA<<<edgeBlks, 256>>>(srcp, dstp, E, N);
    k_passB<<<edgeBlks, 256>>>(srcp, dstp, E, N);
    k_passC<64><<<warpBlks, 256>>>(srcp, dstp, h2, agg2, E, N);

    // ---------- mean over nodes ----------
    k_out_init<<<1, 64>>>(out, b2);
    k_mean<<<256, 256>>>(agg2, out, N, 1.0f / (float)N);
}

// round 4
// speedup vs baseline: 2.5277x; 2.5277x over previous
#include <cuda_runtime.h>
#include <math.h>

// ---------------- problem constants ----------------
#define NMAX 100000
#define EMAX 3200000
#define DHID 128
#define DOUT 64

// ---------------- static scratch (allocation-free) ----------------
__device__ float g_h1   [NMAX * DHID];   // layer1 GEMM out
__device__ float g_agg1 [NMAX * DHID];   // layer1 aggregated (relu+bias fused)
__device__ float g_h2   [NMAX * DOUT];   // layer2 GEMM out
__device__ float g_agg2 [NMAX * DOUT];   // layer2 aggregated
__device__ float g_as   [NMAX];
__device__ float g_ad   [NMAX];
__device__ float g_inv  [NMAX];          // 1/(softmax denom)
__device__ float g_alpha[EMAX + NMAX];   // per-edge exp(e - m[dst]) in CSR order
__device__ int   g_deg  [NMAX];          // in-degree incl. self-loop
__device__ int   g_off  [NMAX];          // CSR segment start
__device__ int   g_cur  [NMAX];          // scatter cursor
__device__ int   g_csrs [EMAX + NMAX];   // CSR src node per edge
__device__ int   g_counter;

// ---------------- small utils ----------------
__global__ void k_fill_int(int* p, int v, int n) {
    int i = blockIdx.x * blockDim.x + threadIdx.x;
    if (i < n) p[i] = v;
}

__device__ __forceinline__ float leaky(float e) { return e > 0.f ? e : 0.2f * e; }

// ---------------- CSR build ----------------
__global__ void k_hist(const int* __restrict__ dstp, int E) {
    int i = blockIdx.x * blockDim.x + threadIdx.x;
    if (i < E) atomicAdd(&g_deg[dstp[i]], 1);
}

// Warp-aggregated offset allocation: no global scan needed; segments just need
// to be contiguous & disjoint, order is irrelevant. Self-loop placed first.
__global__ void k_alloc(int N) {
    int i    = blockIdx.x * blockDim.x + threadIdx.x;
    int lane = threadIdx.x & 31;
    int v    = (i < N) ? g_deg[i] : 0;
    int incl = v;
#pragma unroll
    for (int o = 1; o < 32; o <<= 1) {
        int t = __shfl_up_sync(0xffffffffu, incl, o);
        if (lane >= o) incl += t;
    }
    int total = __shfl_sync(0xffffffffu, incl, 31);
    int base  = 0;
    if (lane == 0) base = atomicAdd(&g_counter, total);
    base = __shfl_sync(0xffffffffu, base, 0);
    if (i < N) {
        int my = base + incl - v;
        g_off[i]  = my;
        g_csrs[my] = i;        // self-loop first in segment
        g_cur[i]  = my + 1;
    }
}

__global__ void k_scatter(const int* __restrict__ srcp, const int* __restrict__ dstp, int E) {
    int i = blockIdx.x * blockDim.x + threadIdx.x;
    if (i < E) {
        int d   = dstp[i];
        int pos = atomicAdd(&g_cur[d], 1);
        g_csrs[pos] = srcp[i];
    }
}

// ---------------- fp32 GEMM: H[N,FOUT] = X[N,128] @ W[128,FOUT] ----------------
template<int FOUT>
__global__ void k_gemm(const float* __restrict__ X, const float* __restrict__ W,
                       float* __restrict__ H, int N) {
    constexpr int K  = 128;
    constexpr int NT = FOUT * 2;
    constexpr int CT = FOUT / 4;
    extern __shared__ float smem[];
    float*  sW  = smem;              // K * FOUT
    float*  sX  = smem + K * FOUT;   // 32 * K
    float4* sW4 = (float4*)sW;
    float4* sX4 = (float4*)sX;

    int tid  = threadIdx.x;
    int row0 = blockIdx.x * 32;

    for (int i = tid; i < K * FOUT / 4; i += NT) sW4[i] = ((const float4*)W)[i];
    {
        const float4* X4 = (const float4*)(X + (size_t)row0 * K);
        int lim = (N - row0) >= 32 ? 32 * K / 4 : (N - row0) * K / 4;
        for (int i = tid; i < lim; i += NT) sX4[i] = X4[i];
    }
    __syncthreads();

    int tx = tid % CT;
    int ty = tid / CT;
    float acc[4][4];
#pragma unroll
    for (int i = 0; i < 4; i++)
#pragma unroll
        for (int j = 0; j < 4; j++) acc[i][j] = 0.f;

    for (int k = 0; k < K; k += 4) {
#pragma unroll
        for (int kk = 0; kk < 4; kk++) {
            float4 wv = sW4[(k + kk) * CT + tx];
#pragma unroll
            for (int i = 0; i < 4; i++) {
                float xv = sX[(ty * 4 + i) * K + k + kk];
                acc[i][0] += xv * wv.x;
                acc[i][1] += xv * wv.y;
                acc[i][2] += xv * wv.z;
                acc[i][3] += xv * wv.w;
            }
        }
    }

    float4* H4 = (float4*)(H + (size_t)row0 * FOUT);
#pragma unroll
    for (int i = 0; i < 4; i++) {
        int r = ty * 4 + i;
        if (row0 + r < N)
            H4[r * CT + tx] = make_float4(acc[i][0], acc[i][1], acc[i][2], acc[i][3]);
    }
}

// ---------------- per-node attention halves ----------------
template<int F>
__global__ void k_dots(const float* __restrict__ H, const float* __restrict__ avs,
                       const float* __restrict__ avd, int N) {
    int w    = (blockIdx.x * blockDim.x + threadIdx.x) >> 5;
    int lane = threadIdx.x & 31;
    if (w >= N) return;
    const float* h = H + (size_t)w * F;
    float s1 = 0.f, s2 = 0.f;
#pragma unroll
    for (int j = 0; j < F / 32; j++) {
        float hv = h[lane + 32 * j];
        s1 += hv * __ldg(&avs[lane + 32 * j]);
        s2 += hv * __ldg(&avd[lane + 32 * j]);
    }
#pragma unroll
    for (int off = 16; off > 0; off >>= 1) {
        s1 += __shfl_down_sync(0xffffffffu, s1, off);
        s2 += __shfl_down_sync(0xffffffffu, s2, off);
    }
    if (lane == 0) { g_as[w] = s1; g_ad[w] = s2; }
}

// ---------------- phase 1: segment softmax per dst node (warp per node) ----------------
__global__ void k_phase1(int N) {
    int w    = (blockIdx.x * blockDim.x + threadIdx.x) >> 5;
    int lane = threadIdx.x & 31;
    if (w >= N) return;
    int   start = g_off[w];
    int   n     = g_deg[w];
    float adv   = g_ad[w];

    if (n <= 32) {
        float e = -INFINITY;
        if (lane < n) {
            int s = g_csrs[start + lane];
            e = leaky(g_as[s] + adv);
        }
        float m = e;
#pragma unroll
        for (int o = 16; o > 0; o >>= 1) m = fmaxf(m, __shfl_xor_sync(0xffffffffu, m, o));
        float ex = (lane < n) ? __expf(e - m) : 0.f;
        float ss = ex;
#pragma unroll
        for (int o = 16; o > 0; o >>= 1) ss += __shfl_xor_sync(0xffffffffu, ss, o);
        if (lane < n) g_alpha[start + lane] = ex;
        if (lane == 0) g_inv[w] = 1.f / (ss + 1e-16f);
    } else {
        float m = -INFINITY;
        for (int j0 = 0; j0 < n; j0 += 32) {
            int j = j0 + lane;
            float e = -INFINITY;
            if (j < n) {
                int s = g_csrs[start + j];
                e = leaky(g_as[s] + adv);
                g_alpha[start + j] = e;
            }
            m = fmaxf(m, e);
        }
#pragma unroll
        for (int o = 16; o > 0; o >>= 1) m = fmaxf(m, __shfl_xor_sync(0xffffffffu, m, o));
        float ss = 0.f;
        for (int j0 = 0; j0 < n; j0 += 32) {
            int j = j0 + lane;
            if (j < n) {
                float ex = __expf(g_alpha[start + j] - m);
                g_alpha[start + j] = ex;
                ss += ex;
            }
        }
#pragma unroll
        for (int o = 16; o > 0; o >>= 1) ss += __shfl_xor_sync(0xffffffffu, ss, o);
        if (lane == 0) g_inv[w] = 1.f / (ss + 1e-16f);
    }
}

// ---------------- phase 2: gather-aggregate per dst node (warp per node) ----------------
template<int F, bool ADD_BIAS, bool RELU>
__global__ void k_phase2(const float* __restrict__ H, float* __restrict__ AGG,
                         const float* __restrict__ bias, int N) {
    int w    = (blockIdx.x * blockDim.x + threadIdx.x) >> 5;
    int lane = threadIdx.x & 31;
    if (w >= N) return;
    int start = g_off[w];
    int n     = g_deg[w];

    if (F == 128) {
        const float4* H4 = (const float4*)H;
        float4 acc = make_float4(0.f, 0.f, 0.f, 0.f);
#pragma unroll 4
        for (int j = 0; j < n; j++) {
            int   s = g_csrs[start + j];
            float a = g_alpha[start + j];
            float4 hv = H4[(size_t)s * 32 + lane];
            acc.x += a * hv.x; acc.y += a * hv.y;
            acc.z += a * hv.z; acc.w += a * hv.w;
        }
        float inv = g_inv[w];
        acc.x *= inv; acc.y *= inv; acc.z *= inv; acc.w *= inv;
        if (ADD_BIAS) {
            float4 bv = ((const float4*)bias)[lane];
            acc.x += bv.x; acc.y += bv.y; acc.z += bv.z; acc.w += bv.w;
        }
        if (RELU) {
            acc.x = fmaxf(acc.x, 0.f); acc.y = fmaxf(acc.y, 0.f);
            acc.z = fmaxf(acc.z, 0.f); acc.w = fmaxf(acc.w, 0.f);
        }
        ((float4*)AGG)[(size_t)w * 32 + lane] = acc;
    } else {
        const float2* H2 = (const float2*)H;
        float2 acc = make_float2(0.f, 0.f);
#pragma unroll 4
        for (int j = 0; j < n; j++) {
            int   s = g_csrs[start + j];
            float a = g_alpha[start + j];
            float2 hv = H2[(size_t)s * 32 + lane];
            acc.x += a * hv.x; acc.y += a * hv.y;
        }
        float inv = g_inv[w];
        acc.x *= inv; acc.y *= inv;
        if (ADD_BIAS) {
            float2 bv = ((const float2*)bias)[lane];
            acc.x += bv.x; acc.y += bv.y;
        }
        if (RELU) { acc.x = fmaxf(acc.x, 0.f); acc.y = fmaxf(acc.y, 0.f); }
        ((float2*)AGG)[(size_t)w * 32 + lane] = acc;
    }
}

// ---------------- output: out[c] = mean_n agg2[n][c] + b2[c] ----------------
__global__ void k_out_init(float* out, const float* __restrict__ b2) {
    if (threadIdx.x < DOUT) out[threadIdx.x] = b2[threadIdx.x];
}

__global__ void k_mean(const float* __restrict__ A, float* out, int N, float invN) {
    int col    = threadIdx.x & 63;
    int rgrp   = blockIdx.x * (blockDim.x >> 6) + (threadIdx.x >> 6);
    int stride = gridDim.x * (blockDim.x >> 6);
    float sum = 0.f;
    for (int n = rgrp; n < N; n += stride) sum += A[(size_t)n * DOUT + col];
    atomicAdd(&out[col], sum * invN);
}

// ---------------- host ----------------
extern "C" void kernel_launch(void* const* d_in, const int* in_sizes, int n_in,
                              void* d_out, int out_size) {
    const float* x   = (const float*)d_in[0];
    const int*   ei  = (const int*)d_in[1];     // int32 (JAX x64 disabled)
    const float* W1  = (const float*)d_in[2];
    const float* a1s = (const float*)d_in[3];
    const float* a1d = (const float*)d_in[4];
    const float* b1  = (const float*)d_in[5];
    const float* W2  = (const float*)d_in[6];
    const float* a2s = (const float*)d_in[7];
    const float* a2d = (const float*)d_in[8];
    const float* b2  = (const float*)d_in[9];
    float* out = (float*)d_out;

    int N = in_sizes[0] / DHID;   // 100000
    int E = in_sizes[1] / 2;      // 3200000
    const int* srcp = ei;
    const int* dstp = ei + E;

    float *h1, *agg1, *h2, *agg2;
    int *degp, *ctrp;
    cudaGetSymbolAddress((void**)&h1,   g_h1);
    cudaGetSymbolAddress((void**)&agg1, g_agg1);
    cudaGetSymbolAddress((void**)&h2,   g_h2);
    cudaGetSymbolAddress((void**)&agg2, g_agg2);
    cudaGetSymbolAddress((void**)&degp, g_deg);
    cudaGetSymbolAddress((void**)&ctrp, g_counter);

    const int smem1 = (128 * 128 + 32 * 128) * 4;  // 81920
    const int smem2 = (128 * 64  + 32 * 128) * 4;  // 49152
    cudaFuncSetAttribute(k_gemm<128>, cudaFuncAttributeMaxDynamicSharedMemorySize, smem1);
    cudaFuncSetAttribute(k_gemm<64>,  cudaFuncAttributeMaxDynamicSharedMemorySize, smem2);

    int gemmBlks = (N + 31) / 32;
    int nodeBlks = (N + 255) / 256;
    int edgeBlks = (E + 255) / 256;
    int warpBlks = (N + 7) / 8;        // 8 warps/block, warp-per-node kernels

    // ---------- CSR build (shared by both layers) ----------
    k_fill_int<<<nodeBlks, 256>>>(degp, 1, N);   // 1 = self-loop
    cudaMemsetAsync(ctrp, 0, sizeof(int));
    k_hist<<<edgeBlks, 256>>>(dstp, E);
    k_alloc<<<nodeBlks, 256>>>(N);
    k_scatter<<<edgeBlks, 256>>>(srcp, dstp, E);

    // ---------- layer 1 (F = 128) ----------
    k_gemm<128><<<gemmBlks, 256, smem1>>>(x, W1, h1, N);
    k_dots<128><<<warpBlks, 256>>>(h1, a1s, a1d, N);
    k_phase1<<<warpBlks, 256>>>(N);
    k_phase2<128, true, true><<<warpBlks, 256>>>(h1, agg1, b1, N);

    // ---------- layer 2 (F = 64) ----------
    k_gemm<64><<<gemmBlks, 128, smem2>>>(agg1, W2, h2, N);
    k_dots<64><<<warpBlks, 256>>>(h2, a2s, a2d, N);
    k_phase1<<<warpBlks, 256>>>(N);
    k_phase2<64, false, false><<<warpBlks, 256>>>(h2, agg2, (const float*)nullptr, N);

    // ---------- mean over nodes (+ b2) ----------
    k_out_init<<<1, 64>>>(out, b2);
    k_mean<<<256, 256>>>(agg2, out, N, 1.0f / (float)N);
}

// round 5
// speedup vs baseline: 2.9409x; 1.1635x over previous
#include <cuda_runtime.h>
#include <cuda_bf16.h>
#include <math.h>

// ---------------- problem constants ----------------
#define NMAX 100000
#define EMAX 3200000
#define DHID 128
#define DOUT 64

// ---------------- static scratch (allocation-free) ----------------
__device__ __nv_bfloat16 g_hb1[NMAX * DHID];   // layer1 GEMM out (bf16 for gather)
__device__ float g_agg1 [NMAX * DHID];         // layer1 aggregated (relu+bias fused)
__device__ __nv_bfloat16 g_hb2[NMAX * DOUT];   // layer2 GEMM out (bf16)
__device__ float g_agg2 [NMAX * DOUT];         // layer2 aggregated
__device__ float g_as   [NMAX];
__device__ float g_ad   [NMAX];
__device__ float g_inv  [NMAX];                // 1/(softmax denom)
__device__ float g_alpha[EMAX + NMAX];         // per-edge exp(e - m) in CSR order
__device__ int   g_deg  [NMAX];
__device__ int   g_off  [NMAX];
__device__ int   g_cur  [NMAX];
__device__ int   g_csrs [EMAX + NMAX];
__device__ int   g_counter;

// ---------------- small utils ----------------
__global__ void k_fill_int(int* p, int v, int n) {
    int i = blockIdx.x * blockDim.x + threadIdx.x;
    if (i < n) p[i] = v;
}

__device__ __forceinline__ float leaky(float e) { return e > 0.f ? e : 0.2f * e; }

// ---------------- CSR build ----------------
__global__ void k_hist(const int* __restrict__ dstp, int E) {
    int i = blockIdx.x * blockDim.x + threadIdx.x;
    if (i < E) atomicAdd(&g_deg[dstp[i]], 1);
}

__global__ void k_alloc(int N) {
    int i    = blockIdx.x * blockDim.x + threadIdx.x;
    int lane = threadIdx.x & 31;
    int v    = (i < N) ? g_deg[i] : 0;
    int incl = v;
#pragma unroll
    for (int o = 1; o < 32; o <<= 1) {
        int t = __shfl_up_sync(0xffffffffu, incl, o);
        if (lane >= o) incl += t;
    }
    int total = __shfl_sync(0xffffffffu, incl, 31);
    int base  = 0;
    if (lane == 0) base = atomicAdd(&g_counter, total);
    base = __shfl_sync(0xffffffffu, base, 0);
    if (i < N) {
        int my = base + incl - v;
        g_off[i]   = my;
        g_csrs[my] = i;        // self-loop first in segment
        g_cur[i]   = my + 1;
    }
}

__global__ void k_scatter(const int* __restrict__ srcp, const int* __restrict__ dstp, int E) {
    int i = blockIdx.x * blockDim.x + threadIdx.x;
    if (i < E) {
        int d   = dstp[i];
        int pos = atomicAdd(&g_cur[d], 1);
        g_csrs[pos] = srcp[i];
    }
}

// ---------------- GEMM (f32x2 packed FMA) + fused dots + bf16 store ----------------
// Block: 64 rows x FOUT cols. Thread tile: 4 rows x 8 cols (cols tx*4..+3 and
// FOUT/2+tx*4..+3 so B pairs load as conflict-free 64-bit LDS).
// Epilogue: bf16 store of h, plus fp32 dot with a_src/a_dst reduced via shfl.
template<int FOUT>
__global__ void k_gemm2(const float* __restrict__ X, const float* __restrict__ W,
                        __nv_bfloat16* __restrict__ HB,
                        const float* __restrict__ avs, const float* __restrict__ avd,
                        int N) {
    constexpr int K  = 128;
    constexpr int BR = 64;
    constexpr int CG = FOUT / 8;   // 16 or 8
    constexpr int NT = CG * 16;    // 256 or 128 threads
    extern __shared__ float smem[];
    float* sW = smem;              // K * FOUT
    float* sX = smem + K * FOUT;   // BR * K

    int tid  = threadIdx.x;
    int row0 = blockIdx.x * BR;

    for (int i = tid; i < K * FOUT / 4; i += NT)
        ((float4*)sW)[i] = ((const float4*)W)[i];
    {
        int rows = N - row0; if (rows > BR) rows = BR;
        const float4* X4 = (const float4*)(X + (size_t)row0 * K);
        for (int i = tid; i < rows * (K / 4); i += NT) ((float4*)sX)[i] = X4[i];
    }
    __syncthreads();

    int tx = tid % CG;
    int ty = tid / CG;
    const unsigned long long* sW2 = (const unsigned long long*)sW;

    unsigned long long acc[4][4];
#pragma unroll
    for (int i = 0; i < 4; i++)
#pragma unroll
        for (int j = 0; j < 4; j++) acc[i][j] = 0ull;

#pragma unroll 4
    for (int k = 0; k < K; k++) {
        unsigned long long b0 = sW2[k * (FOUT / 2) + tx * 2];
        unsigned long long b1 = sW2[k * (FOUT / 2) + tx * 2 + 1];
        unsigned long long b2 = sW2[k * (FOUT / 2) + FOUT / 4 + tx * 2];
        unsigned long long b3 = sW2[k * (FOUT / 2) + FOUT / 4 + tx * 2 + 1];
#pragma unroll
        for (int i = 0; i < 4; i++) {
            unsigned xu = __float_as_uint(sX[(ty * 4 + i) * K + k]);
            unsigned long long a2;
            asm("mov.b64 %0, {%1, %1};" : "=l"(a2) : "r"(xu));
            asm("fma.rn.f32x2 %0, %1, %2, %0;" : "+l"(acc[i][0]) : "l"(a2), "l"(b0));
            asm("fma.rn.f32x2 %0, %1, %2, %0;" : "+l"(acc[i][1]) : "l"(a2), "l"(b1));
            asm("fma.rn.f32x2 %0, %1, %2, %0;" : "+l"(acc[i][2]) : "l"(a2), "l"(b2));
            asm("fma.rn.f32x2 %0, %1, %2, %0;" : "+l"(acc[i][3]) : "l"(a2), "l"(b3));
        }
    }

    // ---- epilogue: unpack, bf16 store, fused attention dots ----
    int c0 = tx * 4, c1 = FOUT / 2 + tx * 4;
    float as0[4], as1[4], ad0[4], ad1[4];
#pragma unroll
    for (int j = 0; j < 4; j++) {
        as0[j] = __ldg(&avs[c0 + j]); as1[j] = __ldg(&avs[c1 + j]);
        ad0[j] = __ldg(&avd[c0 + j]); ad1[j] = __ldg(&avd[c1 + j]);
    }

#pragma unroll
    for (int i = 0; i < 4; i++) {
        int row = row0 + ty * 4 + i;
        float c[8];
#pragma unroll
        for (int j = 0; j < 4; j++) {
            unsigned lo, hi;
            asm("mov.b64 {%0, %1}, %2;" : "=r"(lo), "=r"(hi) : "l"(acc[i][j]));
            c[j * 2]     = __uint_as_float(lo);
            c[j * 2 + 1] = __uint_as_float(hi);
        }
        float s1 = c[0]*as0[0] + c[1]*as0[1] + c[2]*as0[2] + c[3]*as0[3]
                 + c[4]*as1[0] + c[5]*as1[1] + c[6]*as1[2] + c[7]*as1[3];
        float s2 = c[0]*ad0[0] + c[1]*ad0[1] + c[2]*ad0[2] + c[3]*ad0[3]
                 + c[4]*ad1[0] + c[5]*ad1[1] + c[6]*ad1[2] + c[7]*ad1[3];
#pragma unroll
        for (int o = CG / 2; o > 0; o >>= 1) {
            s1 += __shfl_xor_sync(0xffffffffu, s1, o);
            s2 += __shfl_xor_sync(0xffffffffu, s2, o);
        }
        if (row < N) {
            __nv_bfloat162 p0 = __float22bfloat162_rn(make_float2(c[0], c[1]));
            __nv_bfloat162 p1 = __float22bfloat162_rn(make_float2(c[2], c[3]));
            __nv_bfloat162 p2 = __float22bfloat162_rn(make_float2(c[4], c[5]));
            __nv_bfloat162 p3 = __float22bfloat162_rn(make_float2(c[6], c[7]));
            uint2 u, v;
            u.x = *(unsigned*)&p0; u.y = *(unsigned*)&p1;
            v.x = *(unsigned*)&p2; v.y = *(unsigned*)&p3;
            *(uint2*)(HB + (size_t)row * FOUT + c0) = u;
            *(uint2*)(HB + (size_t)row * FOUT + c1) = v;
            if (tx == 0) { g_as[row] = s1; g_ad[row] = s2; }
        }
    }
}

// ---------------- phase 1: segment softmax per dst node (warp per node) ----------------
__global__ void k_phase1(int N) {
    int w    = (blockIdx.x * blockDim.x + threadIdx.x) >> 5;
    int lane = threadIdx.x & 31;
    if (w >= N) return;
    int   start = g_off[w];
    int   n     = g_deg[w];
    float adv   = g_ad[w];

    if (n <= 32) {
        float e = -INFINITY;
        if (lane < n) {
            int s = g_csrs[start + lane];
            e = leaky(g_as[s] + adv);
        }
        float m = e;
#pragma unroll
        for (int o = 16; o > 0; o >>= 1) m = fmaxf(m, __shfl_xor_sync(0xffffffffu, m, o));
        float ex = (lane < n) ? __expf(e - m) : 0.f;
        float ss = ex;
#pragma unroll
        for (int o = 16; o > 0; o >>= 1) ss += __shfl_xor_sync(0xffffffffu, ss, o);
        if (lane < n) g_alpha[start + lane] = ex;
        if (lane == 0) g_inv[w] = 1.f / (ss + 1e-16f);
    } else {
        float m = -INFINITY;
        for (int j0 = 0; j0 < n; j0 += 32) {
            int j = j0 + lane;
            float e = -INFINITY;
            if (j < n) {
                int s = g_csrs[start + j];
                e = leaky(g_as[s] + adv);
                g_alpha[start + j] = e;
            }
            m = fmaxf(m, e);
        }
#pragma unroll
        for (int o = 16; o > 0; o >>= 1) m = fmaxf(m, __shfl_xor_sync(0xffffffffu, m, o));
        float ss = 0.f;
        for (int j0 = 0; j0 < n; j0 += 32) {
            int j = j0 + lane;
            if (j < n) {
                float ex = __expf(g_alpha[start + j] - m);
                g_alpha[start + j] = ex;
                ss += ex;
            }
        }
#pragma unroll
        for (int o = 16; o > 0; o >>= 1) ss += __shfl_xor_sync(0xffffffffu, ss, o);
        if (lane == 0) g_inv[w] = 1.f / (ss + 1e-16f);
    }
}

// ---------------- phase 2: bf16 gather-aggregate (warp per node) ----------------
__global__ void k_phase2_128(const __nv_bfloat16* __restrict__ HB, float* __restrict__ AGG,
                             const float* __restrict__ bias, int N) {
    int w    = (blockIdx.x * blockDim.x + threadIdx.x) >> 5;
    int lane = threadIdx.x & 31;
    if (w >= N) return;
    int start = g_off[w];
    int n     = g_deg[w];
    const uint2* H2 = (const uint2*)HB;   // 128 bf16/row = 32 uint2

    float4 acc = make_float4(0.f, 0.f, 0.f, 0.f);
#pragma unroll 4
    for (int j = 0; j < n; j++) {
        int   s = g_csrs[start + j];
        float a = g_alpha[start + j];
        uint2 v = H2[(size_t)s * 32 + lane];
        float2 f0 = __bfloat1622float2(*(__nv_bfloat162*)&v.x);
        float2 f1 = __bfloat1622float2(*(__nv_bfloat162*)&v.y);
        acc.x += a * f0.x; acc.y += a * f0.y;
        acc.z += a * f1.x; acc.w += a * f1.y;
    }
    float inv = g_inv[w];
    float4 bv = ((const float4*)bias)[lane];
    acc.x = fmaxf(acc.x * inv + bv.x, 0.f);
    acc.y = fmaxf(acc.y * inv + bv.y, 0.f);
    acc.z = fmaxf(acc.z * inv + bv.z, 0.f);
    acc.w = fmaxf(acc.w * inv + bv.w, 0.f);
    ((float4*)AGG)[(size_t)w * 32 + lane] = acc;
}

__global__ void k_phase2_64(const __nv_bfloat16* __restrict__ HB, float* __restrict__ AGG,
                            int N) {
    int w    = (blockIdx.x * blockDim.x + threadIdx.x) >> 5;
    int lane = threadIdx.x & 31;
    if (w >= N) return;
    int start = g_off[w];
    int n     = g_deg[w];
    const unsigned* H1 = (const unsigned*)HB;   // 64 bf16/row = 32 u32

    float2 acc = make_float2(0.f, 0.f);
#pragma unroll 4
    for (int j = 0; j < n; j++) {
        int   s = g_csrs[start + j];
        float a = g_alpha[start + j];
        unsigned v = H1[(size_t)s * 32 + lane];
        float2 f = __bfloat1622float2(*(__nv_bfloat162*)&v);
        acc.x += a * f.x; acc.y += a * f.y;
    }
    float inv = g_inv[w];
    ((float2*)AGG)[(size_t)w * 32 + lane] = make_float2(acc.x * inv, acc.y * inv);
}

// ---------------- output: out[c] = mean_n agg2[n][c] + b2[c] ----------------
__global__ void k_out_init(float* out, const float* __restrict__ b2) {
    if (threadIdx.x < DOUT) out[threadIdx.x] = b2[threadIdx.x];
}

__global__ void k_mean(const float* __restrict__ A, float* out, int N, float invN) {
    int col    = threadIdx.x & 63;
    int rgrp   = blockIdx.x * (blockDim.x >> 6) + (threadIdx.x >> 6);
    int stride = gridDim.x * (blockDim.x >> 6);
    float sum = 0.f;
    for (int n = rgrp; n < N; n += stride) sum += A[(size_t)n * DOUT + col];
    atomicAdd(&out[col], sum * invN);
}

// ---------------- host ----------------
extern "C" void kernel_launch(void* const* d_in, const int* in_sizes, int n_in,
                              void* d_out, int out_size) {
    const float* x   = (const float*)d_in[0];
    const int*   ei  = (const int*)d_in[1];     // int32 (JAX x64 disabled)
    const float* W1  = (const float*)d_in[2];
    const float* a1s = (const float*)d_in[3];
    const float* a1d = (const float*)d_in[4];
    const float* b1  = (const float*)d_in[5];
    const float* W2  = (const float*)d_in[6];
    const float* a2s = (const float*)d_in[7];
    const float* a2d = (const float*)d_in[8];
    const float* b2  = (const float*)d_in[9];
    float* out = (float*)d_out;

    int N = in_sizes[0] / DHID;   // 100000
    int E = in_sizes[1] / 2;      // 3200000
    const int* srcp = ei;
    const int* dstp = ei + E;

    __nv_bfloat16 *hb1, *hb2;
    float *agg1, *agg2;
    int *degp, *ctrp;
    cudaGetSymbolAddress((void**)&hb1,  g_hb1);
    cudaGetSymbolAddress((void**)&agg1, g_agg1);
    cudaGetSymbolAddress((void**)&hb2,  g_hb2);
    cudaGetSymbolAddress((void**)&agg2, g_agg2);
    cudaGetSymbolAddress((void**)&degp, g_deg);
    cudaGetSymbolAddress((void**)&ctrp, g_counter);

    const int smem1 = (128 * 128 + 64 * 128) * 4;  // 96KB
    const int smem2 = (128 * 64  + 64 * 128) * 4;  // 64KB
    cudaFuncSetAttribute(k_gemm2<128>, cudaFuncAttributeMaxDynamicSharedMemorySize, smem1);
    cudaFuncSetAttribute(k_gemm2<64>,  cudaFuncAttributeMaxDynamicSharedMemorySize, smem2);

    int gemmBlks = (N + 63) / 64;
    int nodeBlks = (N + 255) / 256;
    int edgeBlks = (E + 255) / 256;
    int warpBlks = (N + 7) / 8;

    // ---------- CSR build (shared by both layers) ----------
    k_fill_int<<<nodeBlks, 256>>>(degp, 1, N);   // 1 = self-loop
    cudaMemsetAsync(ctrp, 0, sizeof(int));
    k_hist<<<edgeBlks, 256>>>(dstp, E);
    k_alloc<<<nodeBlks, 256>>>(N);
    k_scatter<<<edgeBlks, 256>>>(srcp, dstp, E);

    // ---------- layer 1 (F = 128) ----------
    k_gemm2<128><<<gemmBlks, 256, smem1>>>(x, W1, hb1, a1s, a1d, N);
    k_phase1<<<warpBlks, 256>>>(N);
    k_phase2_128<<<warpBlks, 256>>>(hb1, agg1, b1, N);

    // ---------- layer 2 (F = 64) ----------
    k_gemm2<64><<<gemmBlks, 128, smem2>>>(agg1, W2, hb2, a2s, a2d, N);
    k_phase1<<<warpBlks, 256>>>(N);
    k_phase2_64<<<warpBlks, 256>>>(hb2, agg2, N);

    // ---------- mean over nodes (+ b2) ----------
    k_out_init<<<1, 64>>>(out, b2);
    k_mean<<<256, 256>>>(agg2, out, N, 1.0f / (float)N);
}